// round 1
// baseline (speedup 1.0000x reference)
#include <cuda_runtime.h>

#define NTOK 32768
#define DDIM 2048
#define NGRP 16
#define GSZ  4
#define NEXP 64
#define NROW 20           // 16 group rows + 4 local rows
#define DM_OFF (NTOK * 2)
#define LOSS_OFF (NTOK * 2 + NTOK * NEXP)

// scratch accumulators (no cudaMalloc allowed)
__device__ float g_load[NEXP];
__device__ float g_z[2];

typedef unsigned long long u64;
union F2 { u64 u; float2 f; };

static __device__ __forceinline__ u64 pack2(float lo, float hi) {
    u64 r; asm("mov.b64 %0, {%1,%2};" : "=l"(r) : "f"(lo), "f"(hi)); return r;
}
static __device__ __forceinline__ u64 dup2(float v) {
    u64 r; asm("mov.b64 %0, {%1,%1};" : "=l"(r) : "f"(v)); return r;
}
static __device__ __forceinline__ void fma2(u64 &d, u64 a, u64 b) {
    asm("fma.rn.f32x2 %0, %1, %2, %0;" : "+l"(d) : "l"(a), "l"(b));
}
static __device__ __forceinline__ u64 add2(u64 a, u64 b) {
    u64 r; asm("add.rn.f32x2 %0, %1, %2;" : "=l"(r) : "l"(a), "l"(b)); return r;
}

__global__ void init_scratch() {
    int i = threadIdx.x;
    if (i < NEXP) g_load[i] = 0.f;
    if (i < 2)    g_z[i] = 0.f;
}

__global__ __launch_bounds__(256) void router_main(
    const float* __restrict__ X, const float* __restrict__ Wg,
    const float* __restrict__ We, float* __restrict__ out)
{
    __shared__ float s_load[NEXP];
    __shared__ float s_z[2];
    const int tid = threadIdx.x;
    if (tid < NEXP) s_load[tid] = 0.f;
    if (tid < 2)    s_z[tid] = 0.f;
    __syncthreads();

    const int lane  = tid & 31;
    const int gwarp = (blockIdx.x << 3) + (tid >> 5);
    const int nwarp = gridDim.x << 3;
    float zg = 0.f, zl = 0.f;

    for (int q = gwarp; q < (NTOK >> 2); q += nwarp) {
        const float* x0 = X + (size_t)(4 * q + 0) * DDIM;
        const float* x1 = X + (size_t)(4 * q + 1) * DDIM;
        const float* x2 = X + (size_t)(4 * q + 2) * DDIM;
        const float* x3 = X + (size_t)(4 * q + 3) * DDIM;

        u64 acc[NROW][2];
        #pragma unroll
        for (int r = 0; r < NROW; r++) { acc[r][0] = 0ull; acc[r][1] = 0ull; }

        const int base = lane * 4;
        // prefetch chunk 0 (x streamed with evict-first so weights stay in L1)
        float4 a = __ldcs((const float4*)(x0 + base));
        float4 b = __ldcs((const float4*)(x1 + base));
        float4 c = __ldcs((const float4*)(x2 + base));
        float4 d = __ldcs((const float4*)(x3 + base));

        #pragma unroll 2
        for (int ch = 0; ch < 16; ch++) {
            const int cur = ch * 128 + base;
            const int nxt = (ch < 15) ? (cur + 128) : base;  // clamp: always in-bounds
            float4 na = __ldcs((const float4*)(x0 + nxt));
            float4 nb = __ldcs((const float4*)(x1 + nxt));
            float4 nc = __ldcs((const float4*)(x2 + nxt));
            float4 nd = __ldcs((const float4*)(x3 + nxt));

            // pack x across token-pairs: pA = (t0,t1), pB = (t2,t3)
            u64 pA[4], pB[4];
            pA[0] = pack2(a.x, b.x); pA[1] = pack2(a.y, b.y);
            pA[2] = pack2(a.z, b.z); pA[3] = pack2(a.w, b.w);
            pB[0] = pack2(c.x, d.x); pB[1] = pack2(c.y, d.y);
            pB[2] = pack2(c.z, d.z); pB[3] = pack2(c.w, d.w);

            const float* wgp = Wg + cur;
            #pragma unroll
            for (int r = 0; r < NGRP; r++) {
                float4 w4 = *(const float4*)(wgp + r * DDIM);
                u64 wx = dup2(w4.x), wy = dup2(w4.y), wz = dup2(w4.z), ww = dup2(w4.w);
                fma2(acc[r][0], wx, pA[0]); fma2(acc[r][1], wx, pB[0]);
                fma2(acc[r][0], wy, pA[1]); fma2(acc[r][1], wy, pB[1]);
                fma2(acc[r][0], wz, pA[2]); fma2(acc[r][1], wz, pB[2]);
                fma2(acc[r][0], ww, pA[3]); fma2(acc[r][1], ww, pB[3]);
            }
            const float* wep = We + cur;
            #pragma unroll
            for (int r = 0; r < GSZ; r++) {
                float4 w4 = *(const float4*)(wep + r * DDIM);
                u64 wx = dup2(w4.x), wy = dup2(w4.y), wz = dup2(w4.z), ww = dup2(w4.w);
                fma2(acc[NGRP + r][0], wx, pA[0]); fma2(acc[NGRP + r][1], wx, pB[0]);
                fma2(acc[NGRP + r][0], wy, pA[1]); fma2(acc[NGRP + r][1], wy, pB[1]);
                fma2(acc[NGRP + r][0], wz, pA[2]); fma2(acc[NGRP + r][1], wz, pB[2]);
                fma2(acc[NGRP + r][0], ww, pA[3]); fma2(acc[NGRP + r][1], ww, pB[3]);
            }
            a = na; b = nb; c = nc; d = nd;
        }

        // warp butterfly reduce all 40 packed accumulators (result in every lane)
        #pragma unroll
        for (int r = 0; r < NROW; r++) {
            #pragma unroll
            for (int p = 0; p < 2; p++) {
                u64 v = acc[r][p];
                v = add2(v, __shfl_xor_sync(0xffffffffu, v, 1));
                v = add2(v, __shfl_xor_sync(0xffffffffu, v, 2));
                v = add2(v, __shfl_xor_sync(0xffffffffu, v, 4));
                v = add2(v, __shfl_xor_sync(0xffffffffu, v, 8));
                v = add2(v, __shfl_xor_sync(0xffffffffu, v, 16));
                acc[r][p] = v;
            }
        }

        float fw1 = 0.f, fw2 = 0.f;
        int ei1 = 0, ei2 = 0;
        if (lane < 4) {                       // lane t handles token 4q+t
            const int p = lane >> 1, h = lane & 1;
            float g[NROW];
            #pragma unroll
            for (int r = 0; r < NROW; r++) { F2 u; u.u = acc[r][p]; g[r] = h ? u.f.y : u.f.x; }

            // z-loss partials
            float sg = 0.f, sl = 0.f;
            #pragma unroll
            for (int i = 0; i < NGRP; i++) sg += g[i] * g[i];
            #pragma unroll
            for (int i = NGRP; i < NROW; i++) sl += g[i] * g[i];
            zg += sg; zl += sl;

            // group softmax + top-1 (first-max tie rule, matches jax top_k)
            float m = g[0]; int a0 = 0;
            #pragma unroll
            for (int i = 1; i < NGRP; i++) if (g[i] > m) { m = g[i]; a0 = i; }
            float s = 0.f;
            #pragma unroll
            for (int i = 0; i < NGRP; i++) s += expf(g[i] - m);
            float gw = 1.f / s;               // top-1 prob = exp(0)/s

            // local softmax over 4 + top-2
            float l0 = g[16], l1 = g[17], l2 = g[18], l3 = g[19];
            float m2 = fmaxf(fmaxf(l0, l1), fmaxf(l2, l3));
            float e0 = expf(l0 - m2), e1 = expf(l1 - m2);
            float e2 = expf(l2 - m2), e3 = expf(l3 - m2);
            float s2 = e0 + e1 + e2 + e3;
            float ev[4] = {e0, e1, e2, e3};
            int i1 = 0; float b1 = ev[0];
            #pragma unroll
            for (int j = 1; j < 4; j++) if (ev[j] > b1) { b1 = ev[j]; i1 = j; }
            int i2 = -1; float b2 = -1.f;
            #pragma unroll
            for (int j = 0; j < 4; j++) if (j != i1 && ev[j] > b2) { b2 = ev[j]; i2 = j; }

            float p1v = b1 / s2, p2v = b2 / s2;
            float den = p1v + p2v + 1e-7f;
            fw1 = gw * (p1v / den);
            fw2 = gw * (p2v / den);
            ei1 = (a0 << 2) + i1;
            ei2 = (a0 << 2) + i2;

            int t = 4 * q + lane;
            out[2 * t + 0] = fw1;
            out[2 * t + 1] = fw2;
            atomicAdd(&s_load[ei1], fw1);
            atomicAdd(&s_load[ei2], fw2);
        }

        // dispatch rows: whole warp writes 64 cols per token (coalesced)
        #pragma unroll
        for (int t4 = 0; t4 < 4; t4++) {
            int   a1 = __shfl_sync(0xffffffffu, ei1, t4);
            int   a2 = __shfl_sync(0xffffffffu, ei2, t4);
            float f1 = __shfl_sync(0xffffffffu, fw1, t4);
            float f2 = __shfl_sync(0xffffffffu, fw2, t4);
            float* row = out + DM_OFF + (size_t)(4 * q + t4) * NEXP;
            int c0 = lane, c1 = lane + 32;
            row[c0] = (c0 == a1) ? f1 : ((c0 == a2) ? f2 : 0.f);
            row[c1] = (c1 == a1) ? f1 : ((c1 == a2) ? f2 : 0.f);
        }
    }

    // flush z partials (only lanes 0-3 hold nonzero)
    #pragma unroll
    for (int m = 16; m >= 1; m >>= 1) {
        zg += __shfl_xor_sync(0xffffffffu, zg, m);
        zl += __shfl_xor_sync(0xffffffffu, zl, m);
    }
    if (lane == 0) { atomicAdd(&s_z[0], zg); atomicAdd(&s_z[1], zl); }
    __syncthreads();
    if (tid < NEXP) atomicAdd(&g_load[tid], s_load[tid]);
    if (tid < 2)    atomicAdd(&g_z[tid], s_z[tid]);
}

__global__ void router_finalize(float* __restrict__ out) {
    int i = threadIdx.x;  // 64 threads
    float v = g_load[i];
    float s = v;
    #pragma unroll
    for (int m = 16; m >= 1; m >>= 1) s += __shfl_xor_sync(0xffffffffu, s, m);
    __shared__ float sh[2];
    if ((i & 31) == 0) sh[i >> 5] = s;
    __syncthreads();
    float total = sh[0] + sh[1];
    float target = total * (1.f / NEXP);
    float dv = v - target;
    float sq = dv * dv;
    #pragma unroll
    for (int m = 16; m >= 1; m >>= 1) sq += __shfl_xor_sync(0xffffffffu, sq, m);
    __shared__ float sh2[2];
    if ((i & 31) == 0) sh2[i >> 5] = sq;
    __syncthreads();
    if (i == 0) {
        float lb = (sh2[0] + sh2[1]) * (1.f / NEXP);
        float z = g_z[0] * (1.f / ((float)NTOK * NGRP)) +
                  g_z[1] * (1.f / ((float)NTOK * GSZ));
        out[LOSS_OFF] = 0.001f * (lb + z);
    }
}

extern "C" void kernel_launch(void* const* d_in, const int* in_sizes, int n_in,
                              void* d_out, int out_size) {
    const float* X  = (const float*)d_in[0];
    const float* Wg = (const float*)d_in[1];
    const float* We = (const float*)d_in[2];
    float* out = (float*)d_out;
    init_scratch<<<1, 64>>>();
    router_main<<<148, 256>>>(X, Wg, We, out);
    router_finalize<<<1, 64>>>(out);
}

// round 2
// speedup vs baseline: 2.1520x; 2.1520x over previous
#include <cuda_runtime.h>

#define NTOK 32768
#define DDIM 2048
#define NGRP 16
#define GSZ  4
#define NEXP 64
#define NROW 20
#define DM_OFF (NTOK * 2)
#define LOSS_OFF (NTOK * 2 + NTOK * NEXP)

#define TPB   128                 // threads per block (4 warps)
#define TOKPB 256                 // tokens per block (2 per thread)
#define NBLK  (NTOK / TOKPB)      // 128 blocks
#define KT    64                  // k-tile (floats)
#define NKT   (DDIM / KT)         // 32 tiles
#define XSTR  68                  // padded row stride (floats) -> conflict-free LDS.128
#define XBUF  (TOKPB * XSTR)      // 17408 floats per x buffer
#define WBUF  (NROW * KT)         // 1280 floats per w buffer

// floats: 2 x-bufs + 2 w-bufs + resf(512) + resi(512) + load(64) + z(2)
#define SMEM_FLOATS (2 * XBUF + 2 * WBUF + TOKPB * 2 + TOKPB * 2 + NEXP + 2)
#define SMEM_BYTES  (SMEM_FLOATS * 4)

__device__ float g_load[NEXP];
__device__ float g_z[2];

typedef unsigned long long u64;
union F2 { u64 u; float2 f; };

static __device__ __forceinline__ void fma2(u64 &d, u64 a, u64 b) {
    asm("fma.rn.f32x2 %0, %1, %2, %0;" : "+l"(d) : "l"(a), "l"(b));
}
static __device__ __forceinline__ unsigned s2u(const void* p) {
    return (unsigned)__cvta_generic_to_shared(p);
}
static __device__ __forceinline__ void cpa16(unsigned s, const void* g) {
    asm volatile("cp.async.cg.shared.global [%0], [%1], 16;" :: "r"(s), "l"(g));
}
static __device__ __forceinline__ void cpcommit() { asm volatile("cp.async.commit_group;"); }
static __device__ __forceinline__ void cpwait0()  { asm volatile("cp.async.wait_group 0;"); }

__global__ void init_scratch() {
    int i = threadIdx.x;
    if (i < NEXP) g_load[i] = 0.f;
    if (i < 2)    g_z[i] = 0.f;
}

extern __shared__ float smem[];

__global__ __launch_bounds__(TPB, 1) void router_main(
    const float* __restrict__ X, const float* __restrict__ Wg,
    const float* __restrict__ We, float* __restrict__ out)
{
    float* xs0 = smem;
    float* xs1 = smem + XBUF;
    float* ws0 = smem + 2 * XBUF;
    float* ws1 = smem + 2 * XBUF + WBUF;
    float* resf = smem + 2 * XBUF + 2 * WBUF;       // [256][2] fw1,fw2
    int*   resi = (int*)(resf + TOKPB * 2);          // [256][2] ei1,ei2
    float* s_load = (float*)(resi + TOKPB * 2);      // [64]
    float* s_z = s_load + NEXP;                      // [2]

    const int tid  = threadIdx.x;
    const int lane = tid & 31;
    const int warp = tid >> 5;
    const int T0   = blockIdx.x * TOKPB;

    if (tid < NEXP) s_load[tid] = 0.f;
    if (tid < 2)    s_z[tid] = 0.f;

    const unsigned sx[2] = { s2u(xs0), s2u(xs1) };
    const unsigned sw[2] = { s2u(ws0), s2u(ws1) };

    // ---- stage helpers (cp.async, 16B) ----
    auto stage = [&](int kt, int b) {
        const float* gx = X + (size_t)T0 * DDIM + kt * KT;
        unsigned bx = sx[b];
        #pragma unroll
        for (int i = 0; i < 32; i++) {
            int f = tid + TPB * i;                  // 0..4095 float4s
            int row = f >> 4, c4 = (f & 15) << 2;
            cpa16(bx + (unsigned)(row * XSTR + c4) * 4u,
                  gx + (size_t)row * DDIM + c4);
        }
        unsigned bw = sw[b];
        #pragma unroll
        for (int i = 0; i < 3; i++) {
            int f = tid + TPB * i;
            if (f < NROW * 16) {
                int r = f >> 4, c4 = (f & 15) << 2;
                const float* g = (r < NGRP)
                    ? (Wg + (size_t)r * DDIM + kt * KT + c4)
                    : (We + (size_t)(r - NGRP) * DDIM + kt * KT + c4);
                cpa16(bw + (unsigned)(r * KT + c4) * 4u, g);
            }
        }
        cpcommit();
    };

    u64 acc[NROW][2];
    #pragma unroll
    for (int r = 0; r < NROW; r++) { acc[r][0] = 0ull; acc[r][1] = 0ull; }

    stage(0, 0);
    cpwait0();
    __syncthreads();

    for (int t = 0; t < NKT; t++) {
        if (t + 1 < NKT) stage(t + 1, (t + 1) & 1);

        const float* xb = (t & 1) ? xs1 : xs0;
        const float* wb = (t & 1) ? ws1 : ws0;
        const float* pa = xb + tid * XSTR;           // token a = T0 + tid
        const float* pb = xb + (tid + TPB) * XSTR;   // token b = T0 + tid + 128

        #pragma unroll 2
        for (int kk = 0; kk < KT; kk += 4) {
            ulonglong2 va = *(const ulonglong2*)(pa + kk);   // (x0,x1),(x2,x3) token a
            ulonglong2 vb = *(const ulonglong2*)(pb + kk);   // token b
            #pragma unroll
            for (int r = 0; r < NROW; r++) {
                ulonglong2 w = *(const ulonglong2*)(wb + r * KT + kk); // broadcast
                fma2(acc[r][0], w.x, va.x);
                fma2(acc[r][0], w.y, va.y);
                fma2(acc[r][1], w.x, vb.x);
                fma2(acc[r][1], w.y, vb.y);
            }
        }
        cpwait0();
        __syncthreads();
    }

    // ---- epilogue: each thread owns 2 complete token logit sets ----
    float zg = 0.f, zl = 0.f;
    #pragma unroll
    for (int s = 0; s < 2; s++) {
        const int trow = tid + s * TPB;              // tile row 0..255
        float g[NROW];
        #pragma unroll
        for (int r = 0; r < NROW; r++) { F2 u; u.u = acc[r][s]; g[r] = u.f.x + u.f.y; }

        float sg = 0.f, sl = 0.f;
        #pragma unroll
        for (int i = 0; i < NGRP; i++) sg += g[i] * g[i];
        #pragma unroll
        for (int i = NGRP; i < NROW; i++) sl += g[i] * g[i];
        zg += sg; zl += sl;

        // group softmax + top-1 (first-max tie rule)
        float m = g[0]; int a0 = 0;
        #pragma unroll
        for (int i = 1; i < NGRP; i++) if (g[i] > m) { m = g[i]; a0 = i; }
        float ssum = 0.f;
        #pragma unroll
        for (int i = 0; i < NGRP; i++) ssum += expf(g[i] - m);
        float gw = 1.f / ssum;

        // local softmax over 4 + top-2
        float l0 = g[16], l1 = g[17], l2 = g[18], l3 = g[19];
        float m2 = fmaxf(fmaxf(l0, l1), fmaxf(l2, l3));
        float ev[4] = { expf(l0 - m2), expf(l1 - m2), expf(l2 - m2), expf(l3 - m2) };
        float s2 = ev[0] + ev[1] + ev[2] + ev[3];
        int i1 = 0; float b1 = ev[0];
        #pragma unroll
        for (int j = 1; j < 4; j++) if (ev[j] > b1) { b1 = ev[j]; i1 = j; }
        int i2 = -1; float b2 = -1.f;
        #pragma unroll
        for (int j = 0; j < 4; j++) if (j != i1 && ev[j] > b2) { b2 = ev[j]; i2 = j; }

        float p1v = b1 / s2, p2v = b2 / s2;
        float den = p1v + p2v + 1e-7f;
        float fw1 = gw * (p1v / den);
        float fw2 = gw * (p2v / den);
        int ei1 = (a0 << 2) + i1;
        int ei2 = (a0 << 2) + i2;

        resf[2 * trow] = fw1; resf[2 * trow + 1] = fw2;
        resi[2 * trow] = ei1; resi[2 * trow + 1] = ei2;

        int tok = T0 + trow;
        *(float2*)(out + 2 * tok) = make_float2(fw1, fw2);
        atomicAdd(&s_load[ei1], fw1);
        atomicAdd(&s_load[ei2], fw2);
    }

    // z-loss warp reduce -> smem
    #pragma unroll
    for (int m = 16; m >= 1; m >>= 1) {
        zg += __shfl_xor_sync(0xffffffffu, zg, m);
        zl += __shfl_xor_sync(0xffffffffu, zl, m);
    }
    if (lane == 0) { atomicAdd(&s_z[0], zg); atomicAdd(&s_z[1], zl); }
    __syncthreads();

    // dispatch mask: warp w writes rows [64w, 64w+64), lane writes float2 cols
    #pragma unroll 4
    for (int i = 0; i < 64; i++) {
        int trow = (warp << 6) + i;
        int a1 = resi[2 * trow], a2 = resi[2 * trow + 1];
        float f1 = resf[2 * trow], f2 = resf[2 * trow + 1];
        int c = lane << 1;
        float2 v;
        v.x = (c     == a1) ? f1 : ((c     == a2) ? f2 : 0.f);
        v.y = (c + 1 == a1) ? f1 : ((c + 1 == a2) ? f2 : 0.f);
        *(float2*)(out + DM_OFF + (size_t)(T0 + trow) * NEXP + c) = v;
    }

    if (tid < NEXP) atomicAdd(&g_load[tid], s_load[tid]);
    if (tid < 2)    atomicAdd(&g_z[tid], s_z[tid]);
}

__global__ void router_finalize(float* __restrict__ out) {
    int i = threadIdx.x;  // 64 threads
    float v = g_load[i];
    float s = v;
    #pragma unroll
    for (int m = 16; m >= 1; m >>= 1) s += __shfl_xor_sync(0xffffffffu, s, m);
    __shared__ float sh[2];
    if ((i & 31) == 0) sh[i >> 5] = s;
    __syncthreads();
    float total = sh[0] + sh[1];
    float target = total * (1.f / NEXP);
    float dv = v - target;
    float sq = dv * dv;
    #pragma unroll
    for (int m = 16; m >= 1; m >>= 1) sq += __shfl_xor_sync(0xffffffffu, sq, m);
    __shared__ float sh2[2];
    if ((i & 31) == 0) sh2[i >> 5] = sq;
    __syncthreads();
    if (i == 0) {
        float lb = (sh2[0] + sh2[1]) * (1.f / NEXP);
        float z = g_z[0] * (1.f / ((float)NTOK * NGRP)) +
                  g_z[1] * (1.f / ((float)NTOK * GSZ));
        out[LOSS_OFF] = 0.001f * (lb + z);
    }
}

extern "C" void kernel_launch(void* const* d_in, const int* in_sizes, int n_in,
                              void* d_out, int out_size) {
    const float* X  = (const float*)d_in[0];
    const float* Wg = (const float*)d_in[1];
    const float* We = (const float*)d_in[2];
    float* out = (float*)d_out;

    cudaFuncSetAttribute(router_main,
                         cudaFuncAttributeMaxDynamicSharedMemorySize, SMEM_BYTES);

    init_scratch<<<1, 64>>>();
    router_main<<<NBLK, TPB, SMEM_BYTES>>>(X, Wg, We, out);
    router_finalize<<<1, 64>>>(out);
}